// round 4
// baseline (speedup 1.0000x reference)
#include <cuda_runtime.h>
#include <math.h>
#include <stdint.h>

// Problem constants
#define NB    2
#define TSEQ  2048
#define CDIM  2048
#define NH    16
#define NKV   4
#define HD    128
#define MROWS (NB * TSEQ)          // 4096
#define KVW   (2 * NKV * HD)       // 1024

// Scratch (no cudaMalloc allowed)
__device__ float g_Q[(size_t)MROWS * CDIM];
__device__ float g_KV[(size_t)MROWS * KVW];
__device__ float g_Y[(size_t)MROWS * CDIM];
// pre-rounded (tf32) copies of inputs
__device__ float g_X[(size_t)MROWS * CDIM];
__device__ float g_Wq[(size_t)CDIM * CDIM];
__device__ float g_Wkv[(size_t)KVW * CDIM];
__device__ float g_Wo[(size_t)CDIM * CDIM];

// ---------------------------------------------------------------------------
// Helpers
// ---------------------------------------------------------------------------
__device__ __forceinline__ uint32_t f2tf32(float x) {
    uint32_t r;
    asm("cvt.rna.tf32.f32 %0, %1;\n" : "=r"(r) : "f"(x));
    return r;
}

__device__ __forceinline__ void mma_tf32(float* c,
                                         uint32_t a0, uint32_t a1, uint32_t a2, uint32_t a3,
                                         uint32_t b0, uint32_t b1) {
    asm("mma.sync.aligned.m16n8k8.row.col.f32.tf32.tf32.f32 "
        "{%0,%1,%2,%3}, {%4,%5,%6,%7}, {%8,%9}, {%0,%1,%2,%3};\n"
        : "+f"(c[0]), "+f"(c[1]), "+f"(c[2]), "+f"(c[3])
        : "r"(a0), "r"(a1), "r"(a2), "r"(a3), "r"(b0), "r"(b1));
}

__device__ __forceinline__ void cp_async16(uint32_t smem_addr, const float* gptr) {
    asm volatile("cp.async.cg.shared.global [%0], [%1], 16;\n"
                 :: "r"(smem_addr), "l"(gptr));
}

__device__ __forceinline__ void ldsm_x4(uint32_t& r0, uint32_t& r1, uint32_t& r2, uint32_t& r3,
                                        uint32_t addr) {
    asm volatile("ldmatrix.sync.aligned.m8n8.x4.shared.b16 {%0,%1,%2,%3}, [%4];"
                 : "=r"(r0), "=r"(r1), "=r"(r2), "=r"(r3) : "r"(addr));
}

// ---------------------------------------------------------------------------
// Pre-round fp32 -> tf32 (vectorized elementwise)
// ---------------------------------------------------------------------------
__global__ void round_tf32_kernel(const float* __restrict__ in, float* __restrict__ out, int n4)
{
    int i = blockIdx.x * blockDim.x + threadIdx.x;
    if (i >= n4) return;
    float4 v = ((const float4*)in)[i];
    v.x = __uint_as_float(f2tf32(v.x));
    v.y = __uint_as_float(f2tf32(v.y));
    v.z = __uint_as_float(f2tf32(v.z));
    v.w = __uint_as_float(f2tf32(v.w));
    ((float4*)out)[i] = v;
}

// ---------------------------------------------------------------------------
// TF32 tensor-core NT GEMM: C[M,N] = A[M,K] * B[N,K]^T
// Inputs MUST be pre-rounded to tf32 (raw bits fed to mma).
// 128x128 tile, BK=32, 256 threads, warp tile 64x32, ldmatrix fragment loads.
// ---------------------------------------------------------------------------
#define BKG   32
#define PADK  36
#define TILEF (128 * PADK)

__global__ __launch_bounds__(256, 2) void gemm_tf32_nt(
    const float* __restrict__ A, const float* __restrict__ B,
    float* __restrict__ C, int M, int N, int K)
{
    extern __shared__ float sm[];

    const int tid  = threadIdx.x;
    const int bm   = blockIdx.y * 128;
    const int bn   = blockIdx.x * 128;
    const int warp = tid >> 5;
    const int lane = tid & 31;
    const int wm   = warp >> 2;        // 0..1
    const int wn   = warp & 3;         // 0..3
    const int gid  = lane >> 2;
    const int tig  = lane & 3;
    const int g    = lane & 7;         // ldmatrix row-in-matrix
    const int mset = lane >> 3;        // ldmatrix matrix id 0..3

    // copy indexing: each thread copies one half-row (16 floats) of A and B
    const int crow  = tid >> 1;
    const int cquad = tid & 1;
    const float* gA = A + (size_t)(bm + crow) * K + cquad * 16;
    const float* gB = B + (size_t)(bn + crow) * K + cquad * 16;
    const int soff  = crow * PADK + cquad * 16;

    // ldmatrix base byte-offsets (within a tile buffer, excluding ks term)
    // A matrices: 0:(r+0,c0) 1:(r+8,c0) 2:(r+0,c4) 3:(r+8,c4)
    uint32_t a_off[4];
#pragma unroll
    for (int mt = 0; mt < 4; mt++)
        a_off[mt] = ((wm * 64 + mt * 16 + (mset & 1) * 8 + g) * PADK + (mset >> 1) * 4) * 4;
    // B matrices (per nt-pair): 0:(n+0,c0) 1:(n+0,c4) 2:(n+8,c0) 3:(n+8,c4)
    uint32_t b_off[2];
#pragma unroll
    for (int ntp = 0; ntp < 2; ntp++)
        b_off[ntp] = ((wn * 32 + ntp * 16 + (mset >> 1) * 8 + g) * PADK + (mset & 1) * 4) * 4;

    const uint32_t smA = (uint32_t)__cvta_generic_to_shared(sm);
    const uint32_t smB = smA + 2 * TILEF * 4;

    float acc[4][4][4];
#pragma unroll
    for (int mt = 0; mt < 4; mt++)
#pragma unroll
        for (int nt = 0; nt < 4; nt++)
#pragma unroll
            for (int i = 0; i < 4; i++) acc[mt][nt][i] = 0.f;

    const int niter = K / BKG;

    // prefetch tile 0
    {
        uint32_t sa = smA + soff * 4;
        uint32_t sb = smB + soff * 4;
#pragma unroll
        for (int i = 0; i < 4; i++) {
            cp_async16(sa + i * 16, gA + i * 4);
            cp_async16(sb + i * 16, gB + i * 4);
        }
        asm volatile("cp.async.commit_group;\n" ::: "memory");
    }

    for (int k0 = 0; k0 < niter; k0++) {
        const int buf = k0 & 1;
        if (k0 + 1 < niter) {
            const int koff = (k0 + 1) * BKG;
            uint32_t sa = smA + (buf ^ 1) * TILEF * 4 + soff * 4;
            uint32_t sb = smB + (buf ^ 1) * TILEF * 4 + soff * 4;
#pragma unroll
            for (int i = 0; i < 4; i++) {
                cp_async16(sa + i * 16, gA + koff + i * 4);
                cp_async16(sb + i * 16, gB + koff + i * 4);
            }
        }
        asm volatile("cp.async.commit_group;\n" ::: "memory");
        asm volatile("cp.async.wait_group 1;\n" ::: "memory");
        __syncthreads();

        const uint32_t aBase = smA + buf * TILEF * 4;
        const uint32_t bBase = smB + buf * TILEF * 4;

#pragma unroll
        for (int ks = 0; ks < 4; ks++) {
            const uint32_t kb = ks * 32;   // 8 floats = 32 bytes
            uint32_t af[4][4], bf[4][2];
#pragma unroll
            for (int mt = 0; mt < 4; mt++)
                ldsm_x4(af[mt][0], af[mt][1], af[mt][2], af[mt][3], aBase + a_off[mt] + kb);
#pragma unroll
            for (int ntp = 0; ntp < 2; ntp++)
                ldsm_x4(bf[2*ntp][0], bf[2*ntp][1], bf[2*ntp+1][0], bf[2*ntp+1][1],
                        bBase + b_off[ntp] + kb);
#pragma unroll
            for (int mt = 0; mt < 4; mt++)
#pragma unroll
                for (int nt = 0; nt < 4; nt++)
                    mma_tf32(acc[mt][nt], af[mt][0], af[mt][1], af[mt][2], af[mt][3],
                             bf[nt][0], bf[nt][1]);
        }
        __syncthreads();
    }

#pragma unroll
    for (int mt = 0; mt < 4; mt++) {
        const int r0 = bm + wm * 64 + mt * 16 + gid;
#pragma unroll
        for (int nt = 0; nt < 4; nt++) {
            const int c0 = bn + wn * 32 + nt * 8 + tig * 2;
            *(float2*)&C[(size_t)r0 * N + c0]       = make_float2(acc[mt][nt][0], acc[mt][nt][1]);
            *(float2*)&C[(size_t)(r0 + 8) * N + c0] = make_float2(acc[mt][nt][2], acc[mt][nt][3]);
        }
    }
}

// ---------------------------------------------------------------------------
// RoPE: in-place, layout [rows, nheads, 128], given row stride (floats).
// ---------------------------------------------------------------------------
__global__ void rope_kernel(float* __restrict__ X, int rows, int nheads, int rowstride)
{
    int idx = blockIdx.x * blockDim.x + threadIdx.x;
    int total = rows * nheads * 64;
    if (idx >= total) return;
    int i   = idx & 63;
    int h   = (idx >> 6) % nheads;
    int row = idx / (64 * nheads);
    int t   = row & (TSEQ - 1);

    float freq = expf(-(float)i * (9.210340371976184f / 64.0f));
    float ang = (float)t * freq;
    float s, c;
    sincosf(ang, &s, &c);

    float* p = X + (size_t)row * rowstride + h * 128;
    float x0 = p[i];
    float x1 = p[i + 64];
    p[i]      = x0 * c - x1 * s;
    p[i + 64] = x1 * c + x0 * s;
}

// ---------------------------------------------------------------------------
// Tensor-core causal flash attention (tf32 mma, fp32 softmax).
// Grid: (T/64, H, B), 128 threads (4 warps). Bc=32, cp.async double-buffered.
// Output Y is rounded to tf32 so the O-projection GEMM can skip conversion.
// ---------------------------------------------------------------------------
#define KPAD  132
#define VPAD  136
#define PPAD  36
#define KTILE (32 * KPAD)
#define VTILE (32 * VPAD)
#define BUFSZ (KTILE + VTILE)
#define ATTN_SMEM ((2 * BUFSZ + 64 * PPAD) * 4)   // 77824 bytes

__global__ __launch_bounds__(128, 2) void attn_mma_kernel(
    const float* __restrict__ Q, const float* __restrict__ KV,
    float* __restrict__ Y)
{
    extern __shared__ float sm[];
    float* Ps = sm + 2 * BUFSZ;

    const int b   = blockIdx.z;
    const int h   = blockIdx.y;
    const int q0  = blockIdx.x * 64;
    const int kvh = h >> 2;
    const int tid  = threadIdx.x;
    const int warp = tid >> 5;
    const int lane = tid & 31;
    const int gid  = lane >> 2;
    const int tig  = lane & 3;

    const float scale = 0.08838834764831845f;   // 1/sqrt(128)

    uint32_t qf[16][4];
    {
        const float* qp  = Q + (size_t)(b * TSEQ + q0 + warp * 16 + gid) * CDIM + h * 128;
        const float* qp8 = qp + 8 * CDIM;
#pragma unroll
        for (int ks = 0; ks < 16; ks++) {
            qf[ks][0] = f2tf32(qp [ks * 8 + tig]     * scale);
            qf[ks][1] = f2tf32(qp8[ks * 8 + tig]     * scale);
            qf[ks][2] = f2tf32(qp [ks * 8 + tig + 4] * scale);
            qf[ks][3] = f2tf32(qp8[ks * 8 + tig + 4] * scale);
        }
    }

    float o[16][4];
#pragma unroll
    for (int nt = 0; nt < 16; nt++)
#pragma unroll
        for (int i = 0; i < 4; i++) o[nt][i] = 0.f;
    float m0 = -1e30f, m1 = -1e30f, l0 = 0.f, l1 = 0.f;

    const int nkt = q0 / 32 + 2;

    {
        float* Kb = sm;
        float* Vb = sm + KTILE;
#pragma unroll
        for (int i = 0; i < 8; i++) {
            int idx = tid + i * 128;
            int r = idx >> 5, c4 = idx & 31;
            const float* src = KV + (size_t)(b * TSEQ + r) * KVW + kvh * 128 + c4 * 4;
            cp_async16((uint32_t)__cvta_generic_to_shared(Kb + r * KPAD + c4 * 4), src);
            cp_async16((uint32_t)__cvta_generic_to_shared(Vb + r * VPAD + c4 * 4), src + NKV * HD);
        }
        asm volatile("cp.async.commit_group;\n" ::: "memory");
    }

    const int row0 = warp * 16 + gid;

    for (int t = 0; t < nkt; t++) {
        const int buf = t & 1;
        if (t + 1 < nkt) {
            const int s1 = (t + 1) * 32;
            float* Kb = sm + (buf ^ 1) * BUFSZ;
            float* Vb = Kb + KTILE;
#pragma unroll
            for (int i = 0; i < 8; i++) {
                int idx = tid + i * 128;
                int r = idx >> 5, c4 = idx & 31;
                const float* src = KV + (size_t)(b * TSEQ + s1 + r) * KVW + kvh * 128 + c4 * 4;
                cp_async16((uint32_t)__cvta_generic_to_shared(Kb + r * KPAD + c4 * 4), src);
                cp_async16((uint32_t)__cvta_generic_to_shared(Vb + r * VPAD + c4 * 4), src + NKV * HD);
            }
        }
        asm volatile("cp.async.commit_group;\n" ::: "memory");
        asm volatile("cp.async.wait_group 1;\n" ::: "memory");
        __syncthreads();

        const float* Kb = sm + buf * BUFSZ;
        const float* Vb = Kb + KTILE;
        const int s0 = t * 32;

        float s[4][4];
#pragma unroll
        for (int nt = 0; nt < 4; nt++)
#pragma unroll
            for (int i = 0; i < 4; i++) s[nt][i] = 0.f;

#pragma unroll
        for (int ks = 0; ks < 16; ks++) {
            const int kc = ks * 8;
#pragma unroll
            for (int nt = 0; nt < 4; nt++) {
                const float* kr = Kb + (nt * 8 + gid) * KPAD + kc + tig;
                uint32_t b0 = f2tf32(kr[0]);
                uint32_t b1 = f2tf32(kr[4]);
                mma_tf32(s[nt], qf[ks][0], qf[ks][1], qf[ks][2], qf[ks][3], b0, b1);
            }
        }

        if (t >= nkt - 2) {
            const int r0g = q0 + row0;
#pragma unroll
            for (int nt = 0; nt < 4; nt++) {
                const int c = s0 + nt * 8 + tig * 2;
                if (c > r0g)         s[nt][0] = -1e30f;
                if (c + 1 > r0g)     s[nt][1] = -1e30f;
                if (c > r0g + 8)     s[nt][2] = -1e30f;
                if (c + 1 > r0g + 8) s[nt][3] = -1e30f;
            }
        }

        float rm0 = s[0][0], rm1 = s[0][2];
#pragma unroll
        for (int nt = 0; nt < 4; nt++) {
            rm0 = fmaxf(rm0, fmaxf(s[nt][0], s[nt][1]));
            rm1 = fmaxf(rm1, fmaxf(s[nt][2], s[nt][3]));
        }
        rm0 = fmaxf(rm0, __shfl_xor_sync(0xffffffffu, rm0, 1));
        rm0 = fmaxf(rm0, __shfl_xor_sync(0xffffffffu, rm0, 2));
        rm1 = fmaxf(rm1, __shfl_xor_sync(0xffffffffu, rm1, 1));
        rm1 = fmaxf(rm1, __shfl_xor_sync(0xffffffffu, rm1, 2));

        float mt0 = fmaxf(m0, rm0), mt1 = fmaxf(m1, rm1);
        float c0 = __expf(m0 - mt0), c1 = __expf(m1 - mt1);
        m0 = mt0; m1 = mt1;

        float rs0 = 0.f, rs1 = 0.f;
#pragma unroll
        for (int nt = 0; nt < 4; nt++) {
            s[nt][0] = __expf(s[nt][0] - m0); rs0 += s[nt][0];
            s[nt][1] = __expf(s[nt][1] - m0); rs0 += s[nt][1];
            s[nt][2] = __expf(s[nt][2] - m1); rs1 += s[nt][2];
            s[nt][3] = __expf(s[nt][3] - m1); rs1 += s[nt][3];
        }
        rs0 += __shfl_xor_sync(0xffffffffu, rs0, 1);
        rs0 += __shfl_xor_sync(0xffffffffu, rs0, 2);
        rs1 += __shfl_xor_sync(0xffffffffu, rs1, 1);
        rs1 += __shfl_xor_sync(0xffffffffu, rs1, 2);
        l0 = l0 * c0 + rs0;
        l1 = l1 * c1 + rs1;

#pragma unroll
        for (int nt = 0; nt < 16; nt++) {
            o[nt][0] *= c0; o[nt][1] *= c0;
            o[nt][2] *= c1; o[nt][3] *= c1;
        }

#pragma unroll
        for (int nt = 0; nt < 4; nt++) {
            *(float2*)&Ps[row0 * PPAD + nt * 8 + tig * 2]       = make_float2(s[nt][0], s[nt][1]);
            *(float2*)&Ps[(row0 + 8) * PPAD + nt * 8 + tig * 2] = make_float2(s[nt][2], s[nt][3]);
        }
        __syncwarp();

#pragma unroll
        for (int ks = 0; ks < 4; ks++) {
            const int kc = ks * 8;
            uint32_t a0 = f2tf32(Ps[row0 * PPAD + kc + tig]);
            uint32_t a1 = f2tf32(Ps[(row0 + 8) * PPAD + kc + tig]);
            uint32_t a2 = f2tf32(Ps[row0 * PPAD + kc + tig + 4]);
            uint32_t a3 = f2tf32(Ps[(row0 + 8) * PPAD + kc + tig + 4]);
#pragma unroll
            for (int nt = 0; nt < 16; nt++) {
                uint32_t b0 = f2tf32(Vb[(kc + tig) * VPAD + nt * 8 + gid]);
                uint32_t b1 = f2tf32(Vb[(kc + tig + 4) * VPAD + nt * 8 + gid]);
                mma_tf32(o[nt], a0, a1, a2, a3, b0, b1);
            }
        }
        __syncthreads();
    }

    // write out, pre-rounded to tf32 for the O-projection
    const float inv0 = 1.f / l0, inv1 = 1.f / l1;
    float* yp  = Y + (size_t)(b * TSEQ + q0 + row0) * CDIM + h * 128;
    float* yp8 = yp + 8 * CDIM;
#pragma unroll
    for (int nt = 0; nt < 16; nt++) {
        const int c = nt * 8 + tig * 2;
        *(float2*)&yp [c] = make_float2(__uint_as_float(f2tf32(o[nt][0] * inv0)),
                                        __uint_as_float(f2tf32(o[nt][1] * inv0)));
        *(float2*)&yp8[c] = make_float2(__uint_as_float(f2tf32(o[nt][2] * inv1)),
                                        __uint_as_float(f2tf32(o[nt][3] * inv1)));
    }
}

// ---------------------------------------------------------------------------
extern "C" void kernel_launch(void* const* d_in, const int* in_sizes, int n_in,
                              void* d_out, int out_size)
{
    const float* x   = (const float*)d_in[0];
    const float* Wq  = (const float*)d_in[1];
    const float* Wkv = (const float*)d_in[2];
    const float* Wo  = (const float*)d_in[3];
    float* out = (float*)d_out;

    float *pQ, *pKV, *pY, *pX, *pWq, *pWkv, *pWo;
    cudaGetSymbolAddress((void**)&pQ,   g_Q);
    cudaGetSymbolAddress((void**)&pKV,  g_KV);
    cudaGetSymbolAddress((void**)&pY,   g_Y);
    cudaGetSymbolAddress((void**)&pX,   g_X);
    cudaGetSymbolAddress((void**)&pWq,  g_Wq);
    cudaGetSymbolAddress((void**)&pWkv, g_Wkv);
    cudaGetSymbolAddress((void**)&pWo,  g_Wo);

    const int gemm_smem = 4 * TILEF * sizeof(float);
    cudaFuncSetAttribute(gemm_tf32_nt, cudaFuncAttributeMaxDynamicSharedMemorySize, gemm_smem);
    cudaFuncSetAttribute(attn_mma_kernel, cudaFuncAttributeMaxDynamicSharedMemorySize, ATTN_SMEM);

    // 0) pre-round inputs to tf32
    {
        int n;
        n = MROWS * CDIM / 4;  round_tf32_kernel<<<(n + 255) / 256, 256>>>(x,   pX,   n);
        n = CDIM * CDIM / 4;   round_tf32_kernel<<<(n + 255) / 256, 256>>>(Wq,  pWq,  n);
        n = KVW * CDIM / 4;    round_tf32_kernel<<<(n + 255) / 256, 256>>>(Wkv, pWkv, n);
        n = CDIM * CDIM / 4;   round_tf32_kernel<<<(n + 255) / 256, 256>>>(Wo,  pWo,  n);
    }

    // 1) Q = x @ Wq^T
    gemm_tf32_nt<<<dim3(CDIM / 128, MROWS / 128), 256, gemm_smem>>>(pX, pWq, pQ, MROWS, CDIM, CDIM);
    // 2) KV = x @ Wkv^T
    gemm_tf32_nt<<<dim3(KVW / 128, MROWS / 128), 256, gemm_smem>>>(pX, pWkv, pKV, MROWS, KVW, CDIM);

    // 3) RoPE
    {
        int totQ = MROWS * NH * 64;
        rope_kernel<<<(totQ + 255) / 256, 256>>>(pQ, MROWS, NH, CDIM);
        int totK = MROWS * NKV * 64;
        rope_kernel<<<(totK + 255) / 256, 256>>>(pKV, MROWS, NKV, KVW);
    }

    // 4) tensor-core causal flash attention (writes tf32-rounded Y)
    attn_mma_kernel<<<dim3(TSEQ / 64, NH, NB), 128, ATTN_SMEM>>>(pQ, pKV, pY);

    // 5) out = Y @ Wo^T
    gemm_tf32_nt<<<dim3(CDIM / 128, MROWS / 128), 256, gemm_smem>>>(pY, pWo, out, MROWS, CDIM, CDIM);
}

// round 6
// speedup vs baseline: 1.3587x; 1.3587x over previous
#include <cuda_runtime.h>
#include <math.h>
#include <stdint.h>

// Problem constants
#define NB    2
#define TSEQ  2048
#define CDIM  2048
#define NH    16
#define NKV   4
#define HD    128
#define MROWS (NB * TSEQ)          // 4096
#define KVW   (2 * NKV * HD)       // 1024

// Scratch (no cudaMalloc allowed)
__device__ float g_Q[(size_t)MROWS * CDIM];
__device__ float g_KV[(size_t)MROWS * KVW];
__device__ float g_Y[(size_t)MROWS * CDIM];
// pre-rounded (tf32) copies of inputs
__device__ float g_X[(size_t)MROWS * CDIM];
__device__ float g_Wq[(size_t)CDIM * CDIM];
__device__ float g_Wkv[(size_t)KVW * CDIM];
__device__ float g_Wo[(size_t)CDIM * CDIM];

// ---------------------------------------------------------------------------
// Helpers
// ---------------------------------------------------------------------------
__device__ __forceinline__ uint32_t f2tf32(float x) {
    uint32_t r;
    asm("cvt.rna.tf32.f32 %0, %1;\n" : "=r"(r) : "f"(x));
    return r;
}

__device__ __forceinline__ void mma_tf32(float* c,
                                         uint32_t a0, uint32_t a1, uint32_t a2, uint32_t a3,
                                         uint32_t b0, uint32_t b1) {
    asm("mma.sync.aligned.m16n8k8.row.col.f32.tf32.tf32.f32 "
        "{%0,%1,%2,%3}, {%4,%5,%6,%7}, {%8,%9}, {%0,%1,%2,%3};\n"
        : "+f"(c[0]), "+f"(c[1]), "+f"(c[2]), "+f"(c[3])
        : "r"(a0), "r"(a1), "r"(a2), "r"(a3), "r"(b0), "r"(b1));
}

__device__ __forceinline__ void cp_async16(uint32_t smem_addr, const float* gptr) {
    asm volatile("cp.async.cg.shared.global [%0], [%1], 16;\n"
                 :: "r"(smem_addr), "l"(gptr));
}

// ---------------------------------------------------------------------------
// Pre-round fp32 -> tf32 (vectorized elementwise)
// ---------------------------------------------------------------------------
__global__ void round_tf32_kernel(const float* __restrict__ in, float* __restrict__ out, int n4)
{
    int i = blockIdx.x * blockDim.x + threadIdx.x;
    if (i >= n4) return;
    float4 v = ((const float4*)in)[i];
    v.x = __uint_as_float(f2tf32(v.x));
    v.y = __uint_as_float(f2tf32(v.y));
    v.z = __uint_as_float(f2tf32(v.z));
    v.w = __uint_as_float(f2tf32(v.w));
    ((float4*)out)[i] = v;
}

// ---------------------------------------------------------------------------
// TF32 tensor-core NT GEMM: C[M,N] = A[M,K] * B[N,K]^T  (row-major, row dots)
// Inputs MUST be pre-rounded to tf32; raw bits are fed to mma (no CVT in loop).
// 128x128 tile, BK=32, 256 threads (8 warps 2x4), warp tile 64x32.
// ---------------------------------------------------------------------------
#define BKG   32
#define PADK  36
#define TILEF (128 * PADK)

__global__ __launch_bounds__(256, 2) void gemm_tf32_nt(
    const float* __restrict__ A, const float* __restrict__ B,
    float* __restrict__ C, int M, int N, int K)
{
    extern __shared__ float sm[];
    float* Abuf[2] = { sm,             sm + TILEF };
    float* Bbuf[2] = { sm + 2*TILEF,   sm + 3*TILEF };

    const int tid  = threadIdx.x;
    const int bm   = blockIdx.y * 128;
    const int bn   = blockIdx.x * 128;
    const int warp = tid >> 5;
    const int lane = tid & 31;
    const int wm   = warp >> 2;
    const int wn   = warp & 3;
    const int gid  = lane >> 2;
    const int tig  = lane & 3;

    const int crow  = tid >> 1;
    const int cquad = tid & 1;
    const float* gA = A + (size_t)(bm + crow) * K + cquad * 16;
    const float* gB = B + (size_t)(bn + crow) * K + cquad * 16;
    const int soff  = crow * PADK + cquad * 16;

    float acc[4][4][4];
#pragma unroll
    for (int mt = 0; mt < 4; mt++)
#pragma unroll
        for (int nt = 0; nt < 4; nt++)
#pragma unroll
            for (int i = 0; i < 4; i++) acc[mt][nt][i] = 0.f;

    const int niter = K / BKG;

    {
        uint32_t sa = (uint32_t)__cvta_generic_to_shared(Abuf[0] + soff);
        uint32_t sb = (uint32_t)__cvta_generic_to_shared(Bbuf[0] + soff);
#pragma unroll
        for (int i = 0; i < 4; i++) {
            cp_async16(sa + i * 16, gA + i * 4);
            cp_async16(sb + i * 16, gB + i * 4);
        }
        asm volatile("cp.async.commit_group;\n" ::: "memory");
    }

    for (int k0 = 0; k0 < niter; k0++) {
        const int buf = k0 & 1;
        if (k0 + 1 < niter) {
            const int koff = (k0 + 1) * BKG;
            uint32_t sa = (uint32_t)__cvta_generic_to_shared(Abuf[buf ^ 1] + soff);
            uint32_t sb = (uint32_t)__cvta_generic_to_shared(Bbuf[buf ^ 1] + soff);
#pragma unroll
            for (int i = 0; i < 4; i++) {
                cp_async16(sa + i * 16, gA + koff + i * 4);
                cp_async16(sb + i * 16, gB + koff + i * 4);
            }
        }
        asm volatile("cp.async.commit_group;\n" ::: "memory");
        asm volatile("cp.async.wait_group 1;\n" ::: "memory");
        __syncthreads();

        // raw-bit views: data already tf32-rounded, no CVT needed
        const uint32_t* As = (const uint32_t*)Abuf[buf];
        const uint32_t* Bs = (const uint32_t*)Bbuf[buf];
#pragma unroll
        for (int ks = 0; ks < 4; ks++) {
            const int kc = ks * 8;
            uint32_t af[4][4], bf[4][2];
#pragma unroll
            for (int mt = 0; mt < 4; mt++) {
                const int r = wm * 64 + mt * 16 + gid;
                af[mt][0] = As[r * PADK + kc + tig];
                af[mt][1] = As[(r + 8) * PADK + kc + tig];
                af[mt][2] = As[r * PADK + kc + tig + 4];
                af[mt][3] = As[(r + 8) * PADK + kc + tig + 4];
            }
#pragma unroll
            for (int nt = 0; nt < 4; nt++) {
                const int r = wn * 32 + nt * 8 + gid;
                bf[nt][0] = Bs[r * PADK + kc + tig];
                bf[nt][1] = Bs[r * PADK + kc + tig + 4];
            }
#pragma unroll
            for (int mt = 0; mt < 4; mt++)
#pragma unroll
                for (int nt = 0; nt < 4; nt++)
                    mma_tf32(acc[mt][nt], af[mt][0], af[mt][1], af[mt][2], af[mt][3],
                             bf[nt][0], bf[nt][1]);
        }
        __syncthreads();
    }

#pragma unroll
    for (int mt = 0; mt < 4; mt++) {
        const int r0 = bm + wm * 64 + mt * 16 + gid;
#pragma unroll
        for (int nt = 0; nt < 4; nt++) {
            const int c0 = bn + wn * 32 + nt * 8 + tig * 2;
            *(float2*)&C[(size_t)r0 * N + c0]       = make_float2(acc[mt][nt][0], acc[mt][nt][1]);
            *(float2*)&C[(size_t)(r0 + 8) * N + c0] = make_float2(acc[mt][nt][2], acc[mt][nt][3]);
        }
    }
}

// ---------------------------------------------------------------------------
// RoPE: in-place, layout [rows, nheads, 128], given row stride (floats).
// ---------------------------------------------------------------------------
__global__ void rope_kernel(float* __restrict__ X, int rows, int nheads, int rowstride)
{
    int idx = blockIdx.x * blockDim.x + threadIdx.x;
    int total = rows * nheads * 64;
    if (idx >= total) return;
    int i   = idx & 63;
    int h   = (idx >> 6) % nheads;
    int row = idx / (64 * nheads);
    int t   = row & (TSEQ - 1);

    float freq = expf(-(float)i * (9.210340371976184f / 64.0f));
    float ang = (float)t * freq;
    float s, c;
    sincosf(ang, &s, &c);

    float* p = X + (size_t)row * rowstride + h * 128;
    float x0 = p[i];
    float x1 = p[i + 64];
    p[i]      = x0 * c - x1 * s;
    p[i + 64] = x1 * c + x0 * s;
}

// ---------------------------------------------------------------------------
// Tensor-core causal flash attention (tf32 mma.sync, fp32 softmax).
// Grid: (T/64, H, B), 128 threads (4 warps). Bc=32, cp.async double-buffered.
// Epilogue rounds Y to tf32 so the O-projection GEMM skips conversion.
// ---------------------------------------------------------------------------
#define KPAD  132
#define VPAD  136
#define PPAD  36
#define KTILE (32 * KPAD)
#define VTILE (32 * VPAD)
#define BUFSZ (KTILE + VTILE)
#define ATTN_SMEM ((2 * BUFSZ + 64 * PPAD) * 4)   // 77824 bytes

__global__ __launch_bounds__(128, 2) void attn_mma_kernel(
    const float* __restrict__ Q, const float* __restrict__ KV,
    float* __restrict__ Y)
{
    extern __shared__ float sm[];
    float* Ps = sm + 2 * BUFSZ;

    const int b   = blockIdx.z;
    const int h   = blockIdx.y;
    const int q0  = blockIdx.x * 64;
    const int kvh = h >> 2;
    const int tid  = threadIdx.x;
    const int warp = tid >> 5;
    const int lane = tid & 31;
    const int gid  = lane >> 2;
    const int tig  = lane & 3;

    const float scale = 0.08838834764831845f;   // 1/sqrt(128)

    uint32_t qf[16][4];
    {
        const float* qp  = Q + (size_t)(b * TSEQ + q0 + warp * 16 + gid) * CDIM + h * 128;
        const float* qp8 = qp + 8 * CDIM;
#pragma unroll
        for (int ks = 0; ks < 16; ks++) {
            qf[ks][0] = f2tf32(qp [ks * 8 + tig]     * scale);
            qf[ks][1] = f2tf32(qp8[ks * 8 + tig]     * scale);
            qf[ks][2] = f2tf32(qp [ks * 8 + tig + 4] * scale);
            qf[ks][3] = f2tf32(qp8[ks * 8 + tig + 4] * scale);
        }
    }

    float o[16][4];
#pragma unroll
    for (int nt = 0; nt < 16; nt++)
#pragma unroll
        for (int i = 0; i < 4; i++) o[nt][i] = 0.f;
    float m0 = -1e30f, m1 = -1e30f, l0 = 0.f, l1 = 0.f;

    const int nkt = q0 / 32 + 2;

    {
        float* Kb = sm;
        float* Vb = sm + KTILE;
#pragma unroll
        for (int i = 0; i < 8; i++) {
            int idx = tid + i * 128;
            int r = idx >> 5, c4 = idx & 31;
            const float* src = KV + (size_t)(b * TSEQ + r) * KVW + kvh * 128 + c4 * 4;
            cp_async16((uint32_t)__cvta_generic_to_shared(Kb + r * KPAD + c4 * 4), src);
            cp_async16((uint32_t)__cvta_generic_to_shared(Vb + r * VPAD + c4 * 4), src + NKV * HD);
        }
        asm volatile("cp.async.commit_group;\n" ::: "memory");
    }

    const int row0 = warp * 16 + gid;

    for (int t = 0; t < nkt; t++) {
        const int buf = t & 1;
        if (t + 1 < nkt) {
            const int s1 = (t + 1) * 32;
            float* Kb = sm + (buf ^ 1) * BUFSZ;
            float* Vb = Kb + KTILE;
#pragma unroll
            for (int i = 0; i < 8; i++) {
                int idx = tid + i * 128;
                int r = idx >> 5, c4 = idx & 31;
                const float* src = KV + (size_t)(b * TSEQ + s1 + r) * KVW + kvh * 128 + c4 * 4;
                cp_async16((uint32_t)__cvta_generic_to_shared(Kb + r * KPAD + c4 * 4), src);
                cp_async16((uint32_t)__cvta_generic_to_shared(Vb + r * VPAD + c4 * 4), src + NKV * HD);
            }
        }
        asm volatile("cp.async.commit_group;\n" ::: "memory");
        asm volatile("cp.async.wait_group 1;\n" ::: "memory");
        __syncthreads();

        const float* Kb = sm + buf * BUFSZ;
        const float* Vb = Kb + KTILE;
        const int s0 = t * 32;

        float s[4][4];
#pragma unroll
        for (int nt = 0; nt < 4; nt++)
#pragma unroll
            for (int i = 0; i < 4; i++) s[nt][i] = 0.f;

#pragma unroll
        for (int ks = 0; ks < 16; ks++) {
            const int kc = ks * 8;
#pragma unroll
            for (int nt = 0; nt < 4; nt++) {
                const float* kr = Kb + (nt * 8 + gid) * KPAD + kc + tig;
                uint32_t b0 = f2tf32(kr[0]);
                uint32_t b1 = f2tf32(kr[4]);
                mma_tf32(s[nt], qf[ks][0], qf[ks][1], qf[ks][2], qf[ks][3], b0, b1);
            }
        }

        if (t >= nkt - 2) {
            const int r0g = q0 + row0;
#pragma unroll
            for (int nt = 0; nt < 4; nt++) {
                const int c = s0 + nt * 8 + tig * 2;
                if (c > r0g)         s[nt][0] = -1e30f;
                if (c + 1 > r0g)     s[nt][1] = -1e30f;
                if (c > r0g + 8)     s[nt][2] = -1e30f;
                if (c + 1 > r0g + 8) s[nt][3] = -1e30f;
            }
        }

        float rm0 = s[0][0], rm1 = s[0][2];
#pragma unroll
        for (int nt = 0; nt < 4; nt++) {
            rm0 = fmaxf(rm0, fmaxf(s[nt][0], s[nt][1]));
            rm1 = fmaxf(rm1, fmaxf(s[nt][2], s[nt][3]));
        }
        rm0 = fmaxf(rm0, __shfl_xor_sync(0xffffffffu, rm0, 1));
        rm0 = fmaxf(rm0, __shfl_xor_sync(0xffffffffu, rm0, 2));
        rm1 = fmaxf(rm1, __shfl_xor_sync(0xffffffffu, rm1, 1));
        rm1 = fmaxf(rm1, __shfl_xor_sync(0xffffffffu, rm1, 2));

        float mt0 = fmaxf(m0, rm0), mt1 = fmaxf(m1, rm1);
        float c0 = __expf(m0 - mt0), c1 = __expf(m1 - mt1);
        m0 = mt0; m1 = mt1;

        float rs0 = 0.f, rs1 = 0.f;
#pragma unroll
        for (int nt = 0; nt < 4; nt++) {
            s[nt][0] = __expf(s[nt][0] - m0); rs0 += s[nt][0];
            s[nt][1] = __expf(s[nt][1] - m0); rs0 += s[nt][1];
            s[nt][2] = __expf(s[nt][2] - m1); rs1 += s[nt][2];
            s[nt][3] = __expf(s[nt][3] - m1); rs1 += s[nt][3];
        }
        rs0 += __shfl_xor_sync(0xffffffffu, rs0, 1);
        rs0 += __shfl_xor_sync(0xffffffffu, rs0, 2);
        rs1 += __shfl_xor_sync(0xffffffffu, rs1, 1);
        rs1 += __shfl_xor_sync(0xffffffffu, rs1, 2);
        l0 = l0 * c0 + rs0;
        l1 = l1 * c1 + rs1;

#pragma unroll
        for (int nt = 0; nt < 16; nt++) {
            o[nt][0] *= c0; o[nt][1] *= c0;
            o[nt][2] *= c1; o[nt][3] *= c1;
        }

#pragma unroll
        for (int nt = 0; nt < 4; nt++) {
            *(float2*)&Ps[row0 * PPAD + nt * 8 + tig * 2]       = make_float2(s[nt][0], s[nt][1]);
            *(float2*)&Ps[(row0 + 8) * PPAD + nt * 8 + tig * 2] = make_float2(s[nt][2], s[nt][3]);
        }
        __syncwarp();

#pragma unroll
        for (int ks = 0; ks < 4; ks++) {
            const int kc = ks * 8;
            uint32_t a0 = f2tf32(Ps[row0 * PPAD + kc + tig]);
            uint32_t a1 = f2tf32(Ps[(row0 + 8) * PPAD + kc + tig]);
            uint32_t a2 = f2tf32(Ps[row0 * PPAD + kc + tig + 4]);
            uint32_t a3 = f2tf32(Ps[(row0 + 8) * PPAD + kc + tig + 4]);
#pragma unroll
            for (int nt = 0; nt < 16; nt++) {
                uint32_t b0 = f2tf32(Vb[(kc + tig) * VPAD + nt * 8 + gid]);
                uint32_t b1 = f2tf32(Vb[(kc + tig + 4) * VPAD + nt * 8 + gid]);
                mma_tf32(o[nt], a0, a1, a2, a3, b0, b1);
            }
        }
        __syncthreads();
    }

    // write out, pre-rounded to tf32 for the O-projection
    const float inv0 = 1.f / l0, inv1 = 1.f / l1;
    float* yp  = Y + (size_t)(b * TSEQ + q0 + row0) * CDIM + h * 128;
    float* yp8 = yp + 8 * CDIM;
#pragma unroll
    for (int nt = 0; nt < 16; nt++) {
        const int c = nt * 8 + tig * 2;
        *(float2*)&yp [c] = make_float2(__uint_as_float(f2tf32(o[nt][0] * inv0)),
                                        __uint_as_float(f2tf32(o[nt][1] * inv0)));
        *(float2*)&yp8[c] = make_float2(__uint_as_float(f2tf32(o[nt][2] * inv1)),
                                        __uint_as_float(f2tf32(o[nt][3] * inv1)));
    }
}

// ---------------------------------------------------------------------------
extern "C" void kernel_launch(void* const* d_in, const int* in_sizes, int n_in,
                              void* d_out, int out_size)
{
    const float* x   = (const float*)d_in[0];
    const float* Wq  = (const float*)d_in[1];
    const float* Wkv = (const float*)d_in[2];
    const float* Wo  = (const float*)d_in[3];
    float* out = (float*)d_out;

    float *pQ, *pKV, *pY, *pX, *pWq, *pWkv, *pWo;
    cudaGetSymbolAddress((void**)&pQ,   g_Q);
    cudaGetSymbolAddress((void**)&pKV,  g_KV);
    cudaGetSymbolAddress((void**)&pY,   g_Y);
    cudaGetSymbolAddress((void**)&pX,   g_X);
    cudaGetSymbolAddress((void**)&pWq,  g_Wq);
    cudaGetSymbolAddress((void**)&pWkv, g_Wkv);
    cudaGetSymbolAddress((void**)&pWo,  g_Wo);

    const int gemm_smem = 4 * TILEF * sizeof(float);
    cudaFuncSetAttribute(gemm_tf32_nt, cudaFuncAttributeMaxDynamicSharedMemorySize, gemm_smem);
    cudaFuncSetAttribute(attn_mma_kernel, cudaFuncAttributeMaxDynamicSharedMemorySize, ATTN_SMEM);

    // 0) pre-round inputs to tf32
    {
        int n;
        n = MROWS * CDIM / 4;  round_tf32_kernel<<<(n + 255) / 256, 256>>>(x,   pX,   n);
        n = CDIM * CDIM / 4;   round_tf32_kernel<<<(n + 255) / 256, 256>>>(Wq,  pWq,  n);
        n = KVW * CDIM / 4;    round_tf32_kernel<<<(n + 255) / 256, 256>>>(Wkv, pWkv, n);
        n = CDIM * CDIM / 4;   round_tf32_kernel<<<(n + 255) / 256, 256>>>(Wo,  pWo,  n);
    }

    // 1) Q = x @ Wq^T
    gemm_tf32_nt<<<dim3(CDIM / 128, MROWS / 128), 256, gemm_smem>>>(pX, pWq, pQ, MROWS, CDIM, CDIM);
    // 2) KV = x @ Wkv^T
    gemm_tf32_nt<<<dim3(KVW / 128, MROWS / 128), 256, gemm_smem>>>(pX, pWkv, pKV, MROWS, KVW, CDIM);

    // 3) RoPE
    {
        int totQ = MROWS * NH * 64;
        rope_kernel<<<(totQ + 255) / 256, 256>>>(pQ, MROWS, NH, CDIM);
        int totK = MROWS * NKV * 64;
        rope_kernel<<<(totK + 255) / 256, 256>>>(pKV, MROWS, NKV, KVW);
    }

    // 4) tensor-core causal flash attention (writes tf32-rounded Y)
    attn_mma_kernel<<<dim3(TSEQ / 64, NH, NB), 128, ATTN_SMEM>>>(pQ, pKV, pY);

    // 5) out = Y @ Wo^T
    gemm_tf32_nt<<<dim3(CDIM / 128, MROWS / 128), 256, gemm_smem>>>(pY, pWo, out, MROWS, CDIM, CDIM);
}